// round 5
// baseline (speedup 1.0000x reference)
#include <cuda_runtime.h>
#include <cstdint>

// Problem constants (BertTagger CRF): B=512, T=512, K=128
#define BB 512
#define TT 512
#define KK 128
#define START_TAG 126
#define STOP_TAG 127

__device__ float g_absdiff[BB];
__device__ int   g_order[BB];
__device__ float g_c;       // static per-step scale: log(max_j sum_k exp(trans[j,k])) + slack

typedef unsigned long long ull;

__device__ __forceinline__ ull ffma2(ull a, ull b, ull c) {
    ull d;
    asm("fma.rn.f32x2 %0, %1, %2, %3;" : "=l"(d) : "l"(a), "l"(b), "l"(c));
    return d;
}
__device__ __forceinline__ ull addf2(ull a, ull b) {
    ull d;
    asm("add.rn.f32x2 %0, %1, %2;" : "=l"(d) : "l"(a), "l"(b));
    return d;
}
__device__ __forceinline__ ull packf2(float x, float y) {
    ull d;
    asm("mov.b64 %0, {%1, %2};" : "=l"(d) : "f"(x), "f"(y));
    return d;
}
__device__ __forceinline__ void unpackf2(ull v, float& x, float& y) {
    asm("mov.b64 {%0, %1}, %2;" : "=f"(x), "=f"(y) : "l"(v));
}

// -------- counting-sort ordering: longest sequences get lowest blockIdx ------
__global__ void order_kernel(const int* __restrict__ lengths) {
    __shared__ int hist[TT];
    __shared__ int sfx[TT];
    __shared__ int cur[TT];
    int b = threadIdx.x;
    hist[b] = 0; cur[b] = 0;
    __syncthreads();
    int len = lengths[b];
    int bin = len - 1;
    atomicAdd(&hist[bin], 1);
    __syncthreads();
    sfx[b] = hist[b];
    __syncthreads();
    #pragma unroll
    for (int d = 1; d < TT; d <<= 1) {
        int v = (b + d < TT) ? sfx[b + d] : 0;
        __syncthreads();
        sfx[b] += v;
        __syncthreads();
    }
    int base = (bin < TT - 1) ? sfx[bin + 1] : 0;
    int pos = base + atomicAdd(&cur[bin], 1);
    g_order[pos] = b;
}

// -------- static scale: c = log(max_j sum_k exp(trans[j,k])) + 2.5 ----------
__global__ void shat_kernel(const float* __restrict__ trans) {
    __shared__ float red[4];
    int j = threadIdx.x;  // 128 threads
    float s = 0.0f;
    #pragma unroll 8
    for (int k = 0; k < KK; k++) s += __expf(trans[j * KK + k]);
    #pragma unroll
    for (int o = 16; o > 0; o >>= 1)
        s = fmaxf(s, __shfl_xor_sync(0xffffffffu, s, o));
    if ((j & 31) == 0) red[j >> 5] = s;
    __syncthreads();
    if (j == 0) {
        float mx = fmaxf(fmaxf(red[0], red[1]), fmaxf(red[2], red[3]));
        g_c = __logf(mx) + 2.5f;
    }
}

// -------- block reductions (128 threads, 4 warps) --------
__device__ __forceinline__ float block_max(float v, float* red) {
    #pragma unroll
    for (int o = 16; o > 0; o >>= 1)
        v = fmaxf(v, __shfl_xor_sync(0xffffffffu, v, o));
    if ((threadIdx.x & 31) == 0) red[threadIdx.x >> 5] = v;
    __syncthreads();
    float r = fmaxf(fmaxf(red[0], red[1]), fmaxf(red[2], red[3]));
    __syncthreads();
    return r;
}
__device__ __forceinline__ float block_sum(float v, float* red) {
    #pragma unroll
    for (int o = 16; o > 0; o >>= 1)
        v += __shfl_xor_sync(0xffffffffu, v, o);
    if ((threadIdx.x & 31) == 0) red[threadIdx.x >> 5] = v;
    __syncthreads();
    float r = red[0] + red[1] + red[2] + red[3];
    __syncthreads();
    return r;
}

// -------- main CRF kernel: one CTA per TWO length-paired sequences ----------
__global__ __launch_bounds__(128, 2) void crf_kernel(
    const float* __restrict__ feats,
    const float* __restrict__ trans,
    const int*   __restrict__ tags,
    const int*   __restrict__ lengths)
{
    __shared__ __align__(16) float bufA[2][KK];
    __shared__ __align__(16) float bufB[2][KK];
    __shared__ float wmaxA[4], wmaxB[4];
    __shared__ float red[4];

    const int j = threadIdx.x;
    const int bA = g_order[2 * blockIdx.x];
    const int bB = g_order[2 * blockIdx.x + 1];
    const int lenA = lengths[bA];     // sorted: lenA >= lenB
    const int lenB = lengths[bB];
    const float c = g_c;

    // E row j = exp(trans[j, :]) packed into 64 f32x2 registers (shared by both seqs)
    ull E2[64];
    {
        const float2* tr2 = (const float2*)(trans + j * KK);
        #pragma unroll
        for (int i = 0; i < 64; i++) {
            float2 tv = tr2[i];
            E2[i] = packf2(__expf(tv.x), __expf(tv.y));
        }
    }

    float PA = (j == START_TAG) ? 1.0f : 0.0f;
    float PB = PA;
    float MA = 0.0f, MB = 0.0f;
    bufA[0][j] = PA;
    bufB[0][j] = PB;
    __syncthreads();

    const float* frowA = feats + (size_t)bA * TT * KK;
    const float* frowB = feats + (size_t)bB * TT * KK;
    const unsigned sbaseA = (unsigned)__cvta_generic_to_shared(&bufA[0][0]);
    const unsigned sbaseB = (unsigned)__cvta_generic_to_shared(&bufB[0][0]);

    // emission prefetch pipelines, distance 4
    float eA0 =                frowA[j];
    float eA1 = (1 < lenA) ? frowA[1 * KK + j] : 0.0f;
    float eA2 = (2 < lenA) ? frowA[2 * KK + j] : 0.0f;
    float eA3 = (3 < lenA) ? frowA[3 * KK + j] : 0.0f;
    float eB0 =                frowB[j];
    float eB1 = (1 < lenB) ? frowB[1 * KK + j] : 0.0f;
    float eB2 = (2 < lenB) ? frowB[2 * KK + j] : 0.0f;
    float eB3 = (3 < lenB) ? frowB[3 * KK + j] : 0.0f;

    float corrA = 1.0f, lcorrA = 0.0f;
    float corrB = 1.0f, lcorrB = 0.0f;

    for (int t = 0; t < lenA; t++) {
        float nA = (t + 4 < lenA) ? frowA[(t + 4) * KK + j] : 0.0f;
        float nB = (t + 4 < lenB) ? frowB[(t + 4) * KK + j] : 0.0f;

        const bool activeB = (t < lenB);
        const unsigned sbA = sbaseA + ((unsigned)(t & 1) << 9);
        const unsigned sbB = sbaseB + ((unsigned)(t & 1) << 9);

        // dual dot: 8 independent FMA chains (4 per sequence)
        ull aA0 = 0ull, aA1 = 0ull, aA2 = 0ull, aA3 = 0ull;
        ull aB0 = 0ull, aB1 = 0ull, aB2 = 0ull, aB3 = 0ull;
        #pragma unroll
        for (int i = 0; i < 64; i += 4) {
            ull xa0, xa1, xa2, xa3, xb0, xb1, xb2, xb3;
            asm volatile("ld.shared.v2.b64 {%0,%1},[%2];" : "=l"(xa0), "=l"(xa1) : "r"(sbA + i * 8));
            asm volatile("ld.shared.v2.b64 {%0,%1},[%2];" : "=l"(xa2), "=l"(xa3) : "r"(sbA + i * 8 + 16));
            asm volatile("ld.shared.v2.b64 {%0,%1},[%2];" : "=l"(xb0), "=l"(xb1) : "r"(sbB + i * 8));
            asm volatile("ld.shared.v2.b64 {%0,%1},[%2];" : "=l"(xb2), "=l"(xb3) : "r"(sbB + i * 8 + 16));
            aA0 = ffma2(E2[i + 0], xa0, aA0);
            aB0 = ffma2(E2[i + 0], xb0, aB0);
            aA1 = ffma2(E2[i + 1], xa1, aA1);
            aB1 = ffma2(E2[i + 1], xb1, aB1);
            aA2 = ffma2(E2[i + 2], xa2, aA2);
            aB2 = ffma2(E2[i + 2], xb2, aB2);
            aA3 = ffma2(E2[i + 3], xa3, aA3);
            aB3 = ffma2(E2[i + 3], xb3, aB3);
        }
        ull sA = addf2(addf2(aA0, aA1), addf2(aA2, aA3));
        ull sB = addf2(addf2(aB0, aB1), addf2(aB2, aB3));
        float loA, hiA, loB, hiB;
        unpackf2(sA, loA, hiA);
        unpackf2(sB, loB, hiB);
        float dotA = (loA + hiA) * corrA;
        float dotB = (loB + hiB) * corrB;

        // A always active (t < lenA)
        PA = __expf(eA0 - c) * dotA;
        MA += c + lcorrA;
        corrA = 1.0f; lcorrA = 0.0f;
        if (activeB) {
            PB = __expf(eB0 - c) * dotB;
            MB += c + lcorrB;
            corrB = 1.0f; lcorrB = 0.0f;
        }
        eA0 = eA1; eA1 = eA2; eA2 = eA3; eA3 = nA;
        eB0 = eB1; eB1 = eB2; eB2 = eB3; eB3 = nB;

        if (t != lenA - 1) {
            // lazy renorm every 4 steps: publish warp maxes pre-barrier,
            // consume post-barrier (applied to next step's dot).
            const bool rn = ((t & 3) == 3);
            if (rn) {
                float mvA = PA;
                #pragma unroll
                for (int o = 16; o > 0; o >>= 1)
                    mvA = fmaxf(mvA, __shfl_xor_sync(0xffffffffu, mvA, o));
                if ((j & 31) == 0) wmaxA[j >> 5] = mvA;
                if (activeB) {
                    float mvB = PB;
                    #pragma unroll
                    for (int o = 16; o > 0; o >>= 1)
                        mvB = fmaxf(mvB, __shfl_xor_sync(0xffffffffu, mvB, o));
                    if ((j & 31) == 0) wmaxB[j >> 5] = mvB;
                }
            }
            bufA[(t + 1) & 1][j] = PA;
            if (activeB) bufB[(t + 1) & 1][j] = PB;
            __syncthreads();
            if (rn) {
                float mxA = fmaxf(fmaxf(wmaxA[0], wmaxA[1]), fmaxf(wmaxA[2], wmaxA[3]));
                corrA = __frcp_rn(mxA);
                lcorrA = __logf(mxA);
                if (activeB) {
                    float mxB = fmaxf(fmaxf(wmaxB[0], wmaxB[1]), fmaxf(wmaxB[2], wmaxB[3]));
                    corrB = __frcp_rn(mxB);
                    lcorrB = __logf(mxB);
                }
            }
        }
    }

    // ---- terminals ----
    float termA = __logf(fmaxf(PA, 1e-37f)) + MA + trans[STOP_TAG * KK + j];
    float tmA = block_max(termA, red);
    float ssA = block_sum(__expf(termA - tmA), red);
    float fwdA = tmA + __logf(ssA);

    float termB = __logf(fmaxf(PB, 1e-37f)) + MB + trans[STOP_TAG * KK + j];
    float tmB = block_max(termB, red);
    float ssB = block_sum(__expf(termB - tmB), red);
    float fwdB = tmB + __logf(ssB);

    // ---- gold scores ----
    {
        const int* trow = tags + bA * TT;
        float g = 0.0f;
        for (int t = j; t < TT; t += 128) {
            if (t < lenA) {
                int tag  = trow[t];
                int prev = (t == 0) ? START_TAG : trow[t - 1];
                g += trans[tag * KK + prev] + frowA[t * KK + tag];
            }
        }
        if (j == 0) g += trans[STOP_TAG * KK + trow[lenA - 1]];
        float gold = block_sum(g, red);
        if (j == 0) g_absdiff[bA] = fabsf(fwdA - gold);
    }
    {
        const int* trow = tags + bB * TT;
        float g = 0.0f;
        for (int t = j; t < TT; t += 128) {
            if (t < lenB) {
                int tag  = trow[t];
                int prev = (t == 0) ? START_TAG : trow[t - 1];
                g += trans[tag * KK + prev] + frowB[t * KK + tag];
            }
        }
        if (j == 0) g += trans[STOP_TAG * KK + trow[lenB - 1]];
        float gold = block_sum(g, red);
        if (j == 0) g_absdiff[bB] = fabsf(fwdB - gold);
    }
}

// -------- deterministic final reduction --------
__global__ void reduce_kernel(float* __restrict__ out, int out_size) {
    __shared__ float s[BB];
    int t = threadIdx.x;
    s[t] = g_absdiff[t];
    __syncthreads();
    #pragma unroll
    for (int off = 256; off > 0; off >>= 1) {
        if (t < off) s[t] += s[t + off];
        __syncthreads();
    }
    float r = s[0] * (1.0f / (float)BB);
    for (int i = t; i < out_size; i += BB) out[i] = r;
}

extern "C" void kernel_launch(void* const* d_in, const int* in_sizes, int n_in,
                              void* d_out, int out_size) {
    const float* feats   = nullptr;
    const float* trans   = nullptr;
    const int*   tags    = nullptr;
    const int*   lengths = nullptr;
    for (int i = 0; i < n_in; i++) {
        switch (in_sizes[i]) {
            case BB * TT * KK: feats   = (const float*)d_in[i]; break;  // 33554432
            case KK * KK:      trans   = (const float*)d_in[i]; break;  // 16384
            case BB * TT:      tags    = (const int*)d_in[i];   break;  // 262144
            case BB:           lengths = (const int*)d_in[i];   break;  // 512
            default: break;
        }
    }

    order_kernel<<<1, BB>>>(lengths);
    shat_kernel<<<1, KK>>>(trans);
    crf_kernel<<<BB / 2, 128>>>(feats, trans, tags, lengths);
    reduce_kernel<<<1, BB>>>((float*)d_out, out_size);
}

// round 6
// speedup vs baseline: 1.2078x; 1.2078x over previous
#include <cuda_runtime.h>
#include <cstdint>

// Problem constants (BertTagger CRF): B=512, T=512, K=128
#define BB 512
#define TT 512
#define KK 128
#define START_TAG 126
#define STOP_TAG 127

__device__ float g_absdiff[BB];
__device__ int   g_order[BB];
__device__ float g_c;       // static per-step scale: log(max_j sum_k exp(trans[j,k])) + slack

typedef unsigned long long ull;

__device__ __forceinline__ ull ffma2(ull a, ull b, ull c) {
    ull d;
    asm("fma.rn.f32x2 %0, %1, %2, %3;" : "=l"(d) : "l"(a), "l"(b), "l"(c));
    return d;
}
__device__ __forceinline__ ull addf2(ull a, ull b) {
    ull d;
    asm("add.rn.f32x2 %0, %1, %2;" : "=l"(d) : "l"(a), "l"(b));
    return d;
}
__device__ __forceinline__ ull packf2(float x, float y) {
    ull d;
    asm("mov.b64 %0, {%1, %2};" : "=l"(d) : "f"(x), "f"(y));
    return d;
}
__device__ __forceinline__ void unpackf2(ull v, float& x, float& y) {
    asm("mov.b64 {%0, %1}, %2;" : "=f"(x), "=f"(y) : "l"(v));
}

// -------- counting-sort ordering: longest sequences get lowest blockIdx ------
__global__ void order_kernel(const int* __restrict__ lengths) {
    __shared__ int hist[TT];
    __shared__ int sfx[TT];
    __shared__ int cur[TT];
    int b = threadIdx.x;
    hist[b] = 0; cur[b] = 0;
    __syncthreads();
    int len = lengths[b];
    int bin = len - 1;
    atomicAdd(&hist[bin], 1);
    __syncthreads();
    sfx[b] = hist[b];
    __syncthreads();
    #pragma unroll
    for (int d = 1; d < TT; d <<= 1) {
        int v = (b + d < TT) ? sfx[b + d] : 0;
        __syncthreads();
        sfx[b] += v;
        __syncthreads();
    }
    int base = (bin < TT - 1) ? sfx[bin + 1] : 0;
    int pos = base + atomicAdd(&cur[bin], 1);
    g_order[pos] = b;
}

// -------- static scale: c = log(max_j sum_k exp(trans[j,k])) + 2.5 ----------
__global__ void shat_kernel(const float* __restrict__ trans) {
    __shared__ float red[4];
    int j = threadIdx.x;  // 128 threads
    float s = 0.0f;
    #pragma unroll 8
    for (int k = 0; k < KK; k++) s += __expf(trans[j * KK + k]);
    #pragma unroll
    for (int o = 16; o > 0; o >>= 1)
        s = fmaxf(s, __shfl_xor_sync(0xffffffffu, s, o));
    if ((j & 31) == 0) red[j >> 5] = s;
    __syncthreads();
    if (j == 0) {
        float mx = fmaxf(fmaxf(red[0], red[1]), fmaxf(red[2], red[3]));
        g_c = __logf(mx) + 2.5f;
    }
}

// -------- dummy 3rd launch so crf_kernel is the 4th (ncu captures launch #4) --
__global__ void zinit_kernel() {
    g_absdiff[threadIdx.x + blockIdx.x * blockDim.x] = 0.0f;
}

// -------- block reductions (128 threads, 4 warps) --------
__device__ __forceinline__ float block_max(float v, float* red) {
    #pragma unroll
    for (int o = 16; o > 0; o >>= 1)
        v = fmaxf(v, __shfl_xor_sync(0xffffffffu, v, o));
    if ((threadIdx.x & 31) == 0) red[threadIdx.x >> 5] = v;
    __syncthreads();
    float r = fmaxf(fmaxf(red[0], red[1]), fmaxf(red[2], red[3]));
    __syncthreads();
    return r;
}
__device__ __forceinline__ float block_sum(float v, float* red) {
    #pragma unroll
    for (int o = 16; o > 0; o >>= 1)
        v += __shfl_xor_sync(0xffffffffu, v, o);
    if ((threadIdx.x & 31) == 0) red[threadIdx.x >> 5] = v;
    __syncthreads();
    float r = red[0] + red[1] + red[2] + red[3];
    __syncthreads();
    return r;
}

// -------- main CRF kernel: one CTA per batch element --------
__global__ __launch_bounds__(128, 3) void crf_kernel(
    const float* __restrict__ feats,
    const float* __restrict__ trans,
    const int*   __restrict__ tags,
    const int*   __restrict__ lengths)
{
    __shared__ __align__(16) float buf[2][KK];  // double-buffered P = exp(alpha - M)
    __shared__ float wmax[4];
    __shared__ float red[4];

    const int j = threadIdx.x;
    const int b = g_order[blockIdx.x];
    const int len = lengths[b];
    const float c = g_c;

    // E row j = exp(trans[j, :]) packed into 64 f32x2 registers
    ull E2[64];
    {
        const float2* tr2 = (const float2*)(trans + j * KK);
        #pragma unroll
        for (int i = 0; i < 64; i++) {
            float2 tv = tr2[i];
            E2[i] = packf2(__expf(tv.x), __expf(tv.y));
        }
    }

    // init: P0 one-hot at START, M = 0
    float P = (j == START_TAG) ? 1.0f : 0.0f;
    float M = 0.0f;
    buf[0][j] = P;
    __syncthreads();

    const float* frow = feats + (size_t)b * TT * KK;
    const unsigned sbase = (unsigned)__cvta_generic_to_shared(&buf[0][0]);

    // emission prefetch pipeline, distance 4
    float e0 =               frow[j];
    float e1 = (1 < len) ? frow[1 * KK + j] : 0.0f;
    float e2 = (2 < len) ? frow[2 * KK + j] : 0.0f;
    float e3 = (3 < len) ? frow[3 * KK + j] : 0.0f;

    float corr = 1.0f;   // dot multiplier from lazy renorm (applied one step late)
    float lcorr = 0.0f;  // matching log-scale addition to M

    for (int t = 0; t < len; t++) {
        // prefetch emission for step t+4
        float e4 = 0.0f;
        if (t + 4 < len) e4 = frow[(t + 4) * KK + j];

        // dot_j = sum_k E[j,k] * P_prev[k]   (packed f32x2, 4 chains)
        const unsigned sb = sbase + ((unsigned)(t & 1) << 9);
        ull a0 = 0ull, a1 = 0ull, a2 = 0ull, a3 = 0ull;
        #pragma unroll
        for (int i = 0; i < 64; i += 8) {
            ull x0, x1, x2, x3, x4, x5, x6, x7;
            asm volatile("ld.shared.v2.b64 {%0,%1},[%2];" : "=l"(x0), "=l"(x1) : "r"(sb + i * 8));
            asm volatile("ld.shared.v2.b64 {%0,%1},[%2];" : "=l"(x2), "=l"(x3) : "r"(sb + i * 8 + 16));
            asm volatile("ld.shared.v2.b64 {%0,%1},[%2];" : "=l"(x4), "=l"(x5) : "r"(sb + i * 8 + 32));
            asm volatile("ld.shared.v2.b64 {%0,%1},[%2];" : "=l"(x6), "=l"(x7) : "r"(sb + i * 8 + 48));
            a0 = ffma2(E2[i + 0], x0, a0);
            a1 = ffma2(E2[i + 1], x1, a1);
            a2 = ffma2(E2[i + 2], x2, a2);
            a3 = ffma2(E2[i + 3], x3, a3);
            a0 = ffma2(E2[i + 4], x4, a0);
            a1 = ffma2(E2[i + 5], x5, a1);
            a2 = ffma2(E2[i + 6], x6, a2);
            a3 = ffma2(E2[i + 7], x7, a3);
        }
        ull s = addf2(addf2(a0, a1), addf2(a2, a3));
        float lo, hi;
        unpackf2(s, lo, hi);
        float dot = (lo + hi) * corr;

        // P_new = exp(emit - c) * dot ;  alpha = log P + M
        P = __expf(e0 - c) * dot;
        M += c + lcorr;
        corr = 1.0f; lcorr = 0.0f;
        e0 = e1; e1 = e2; e2 = e3; e3 = e4;

        if (t != len - 1) {
            // lazy renorm: publish warp maxes through this step's barrier;
            // applied to next step's dot (off the critical path).
            bool rn = ((t & 3) == 3);
            if (rn) {
                float mv = P;
                #pragma unroll
                for (int o = 16; o > 0; o >>= 1)
                    mv = fmaxf(mv, __shfl_xor_sync(0xffffffffu, mv, o));
                if ((j & 31) == 0) wmax[j >> 5] = mv;
            }
            buf[(t + 1) & 1][j] = P;
            __syncthreads();
            if (rn) {
                float mx = fmaxf(fmaxf(wmax[0], wmax[1]), fmaxf(wmax[2], wmax[3]));
                corr = __frcp_rn(mx);
                lcorr = __logf(mx);
            }
        }
    }

    // terminal: logsumexp_j( alpha[j] + trans[STOP, j] ),  alpha = log P + M
    float term = __logf(fmaxf(P, 1e-37f)) + M + trans[STOP_TAG * KK + j];
    float tm = block_max(term, red);
    float ssum = block_sum(__expf(term - tm), red);
    float fwd = tm + __logf(ssum);

    // gold score
    const int* trow = tags + b * TT;
    float g = 0.0f;
    for (int t = j; t < TT; t += 128) {
        if (t < len) {
            int tag  = trow[t];
            int prev = (t == 0) ? START_TAG : trow[t - 1];
            g += trans[tag * KK + prev] + frow[t * KK + tag];
        }
    }
    if (j == 0) g += trans[STOP_TAG * KK + trow[len - 1]];
    float gold = block_sum(g, red);

    if (j == 0) g_absdiff[b] = fabsf(fwd - gold);
}

// -------- deterministic final reduction --------
__global__ void reduce_kernel(float* __restrict__ out, int out_size) {
    __shared__ float s[BB];
    int t = threadIdx.x;
    s[t] = g_absdiff[t];
    __syncthreads();
    #pragma unroll
    for (int off = 256; off > 0; off >>= 1) {
        if (t < off) s[t] += s[t + off];
        __syncthreads();
    }
    float r = s[0] * (1.0f / (float)BB);
    for (int i = t; i < out_size; i += BB) out[i] = r;
}

extern "C" void kernel_launch(void* const* d_in, const int* in_sizes, int n_in,
                              void* d_out, int out_size) {
    const float* feats   = nullptr;
    const float* trans   = nullptr;
    const int*   tags    = nullptr;
    const int*   lengths = nullptr;
    for (int i = 0; i < n_in; i++) {
        switch (in_sizes[i]) {
            case BB * TT * KK: feats   = (const float*)d_in[i]; break;  // 33554432
            case KK * KK:      trans   = (const float*)d_in[i]; break;  // 16384
            case BB * TT:      tags    = (const int*)d_in[i];   break;  // 262144
            case BB:           lengths = (const int*)d_in[i];   break;  // 512
            default: break;
        }
    }

    // Launch order chosen so crf_kernel is launch #4 — the one ncu captures.
    order_kernel<<<1, BB>>>(lengths);
    shat_kernel<<<1, KK>>>(trans);
    zinit_kernel<<<1, BB>>>();
    crf_kernel<<<BB, 128>>>(feats, trans, tags, lengths);
    reduce_kernel<<<1, BB>>>((float*)d_out, out_size);
}

// round 7
// speedup vs baseline: 1.3931x; 1.1534x over previous
#include <cuda_runtime.h>
#include <cstdint>

// Problem constants (BertTagger CRF): B=512, T=512, K=128
#define BB 512
#define TT 512
#define KK 128
#define START_TAG 126
#define STOP_TAG 127
#define NTHR 256   // 2 threads per tag j (k-split halves)

__device__ float g_absdiff[BB];
__device__ int   g_order[BB];
__device__ float g_c;       // static per-step scale: log(max_j sum_k exp(trans[j,k])) + slack

typedef unsigned long long ull;

__device__ __forceinline__ ull ffma2(ull a, ull b, ull c) {
    ull d;
    asm("fma.rn.f32x2 %0, %1, %2, %3;" : "=l"(d) : "l"(a), "l"(b), "l"(c));
    return d;
}
__device__ __forceinline__ ull addf2(ull a, ull b) {
    ull d;
    asm("add.rn.f32x2 %0, %1, %2;" : "=l"(d) : "l"(a), "l"(b));
    return d;
}
__device__ __forceinline__ ull packf2(float x, float y) {
    ull d;
    asm("mov.b64 %0, {%1, %2};" : "=l"(d) : "f"(x), "f"(y));
    return d;
}
__device__ __forceinline__ void unpackf2(ull v, float& x, float& y) {
    asm("mov.b64 {%0, %1}, %2;" : "=f"(x), "=f"(y) : "l"(v));
}

// -------- counting-sort ordering: longest sequences get lowest blockIdx ------
__global__ void order_kernel(const int* __restrict__ lengths) {
    __shared__ int hist[TT];
    __shared__ int sfx[TT];
    __shared__ int cur[TT];
    int b = threadIdx.x;
    hist[b] = 0; cur[b] = 0;
    __syncthreads();
    int len = lengths[b];
    int bin = len - 1;
    atomicAdd(&hist[bin], 1);
    __syncthreads();
    sfx[b] = hist[b];
    __syncthreads();
    #pragma unroll
    for (int d = 1; d < TT; d <<= 1) {
        int v = (b + d < TT) ? sfx[b + d] : 0;
        __syncthreads();
        sfx[b] += v;
        __syncthreads();
    }
    int base = (bin < TT - 1) ? sfx[bin + 1] : 0;
    int pos = base + atomicAdd(&cur[bin], 1);
    g_order[pos] = b;
}

// -------- static scale: c = log(max_j sum_k exp(trans[j,k])) + 2.5 ----------
__global__ void shat_kernel(const float* __restrict__ trans) {
    __shared__ float red[4];
    int j = threadIdx.x;  // 128 threads
    float s = 0.0f;
    #pragma unroll 8
    for (int k = 0; k < KK; k++) s += __expf(trans[j * KK + k]);
    #pragma unroll
    for (int o = 16; o > 0; o >>= 1)
        s = fmaxf(s, __shfl_xor_sync(0xffffffffu, s, o));
    if ((j & 31) == 0) red[j >> 5] = s;
    __syncthreads();
    if (j == 0) {
        float mx = fmaxf(fmaxf(red[0], red[1]), fmaxf(red[2], red[3]));
        g_c = __logf(mx) + 2.5f;
    }
}

// -------- dummy 3rd launch so crf_kernel is the 4th (ncu captures launch #4) --
__global__ void zinit_kernel() {
    g_absdiff[threadIdx.x + blockIdx.x * blockDim.x] = 0.0f;
}

// -------- block reductions (256 threads, 8 warps) --------
__device__ __forceinline__ float block_max8(float v, float* red) {
    #pragma unroll
    for (int o = 16; o > 0; o >>= 1)
        v = fmaxf(v, __shfl_xor_sync(0xffffffffu, v, o));
    if ((threadIdx.x & 31) == 0) red[threadIdx.x >> 5] = v;
    __syncthreads();
    float r = fmaxf(fmaxf(fmaxf(red[0], red[1]), fmaxf(red[2], red[3])),
                    fmaxf(fmaxf(red[4], red[5]), fmaxf(red[6], red[7])));
    __syncthreads();
    return r;
}
__device__ __forceinline__ float block_sum8(float v, float* red) {
    #pragma unroll
    for (int o = 16; o > 0; o >>= 1)
        v += __shfl_xor_sync(0xffffffffu, v, o);
    if ((threadIdx.x & 31) == 0) red[threadIdx.x >> 5] = v;
    __syncthreads();
    float r = ((red[0] + red[1]) + (red[2] + red[3]))
            + ((red[4] + red[5]) + (red[6] + red[7]));
    __syncthreads();
    return r;
}

// -------- main CRF kernel: one CTA per batch element, 2 threads per tag -----
__global__ __launch_bounds__(NTHR, 2) void crf_kernel(
    const float* __restrict__ feats,
    const float* __restrict__ trans,
    const int*   __restrict__ tags,
    const int*   __restrict__ lengths)
{
    __shared__ __align__(16) float buf[2][KK];  // double-buffered P = exp(alpha - M)
    __shared__ float wmax[8];
    __shared__ float red[8];

    const int tid = threadIdx.x;
    const int j = tid >> 1;        // tag index
    const int h = tid & 1;         // k-half selector
    const int b = g_order[blockIdx.x];
    const int len = lengths[b];
    const float c = g_c;

    // Half of E row j: interleaved 16B chunks k = 8c+4h .. 8c+4h+3, c=0..15.
    // 32 f32x2 registers (64 regs) instead of 64 (128 regs).
    ull E2[32];
    {
        #pragma unroll
        for (int cc = 0; cc < 16; cc++) {
            float4 tv = *(const float4*)(trans + j * KK + 8 * cc + 4 * h);
            E2[2 * cc]     = packf2(__expf(tv.x), __expf(tv.y));
            E2[2 * cc + 1] = packf2(__expf(tv.z), __expf(tv.w));
        }
    }

    // init: P0 one-hot at START, M = 0
    float P = (j == START_TAG) ? 1.0f : 0.0f;
    float M = 0.0f;
    if (h == 0) buf[0][j] = P;
    __syncthreads();

    const float* frow = feats + (size_t)b * TT * KK;
    const unsigned sbase = (unsigned)__cvta_generic_to_shared(&buf[0][0]) + (unsigned)(h << 4);

    // emission prefetch pipeline, distance 4 (pair loads same addr — coalesced)
    float e0 =               frow[j];
    float e1 = (1 < len) ? frow[1 * KK + j] : 0.0f;
    float e2 = (2 < len) ? frow[2 * KK + j] : 0.0f;
    float e3 = (3 < len) ? frow[3 * KK + j] : 0.0f;

    float corr = 1.0f;   // dot multiplier from lazy renorm (applied one step late)
    float lcorr = 0.0f;  // matching log-scale addition to M

    for (int t = 0; t < len; t++) {
        // prefetch emission for step t+4
        float e4 = 0.0f;
        if (t + 4 < len) e4 = frow[(t + 4) * KK + j];

        // partial dot over own 64 k's: 16 chunks x 16B, 4 FMA chains
        const unsigned sb = sbase + ((unsigned)(t & 1) << 9);
        ull a0 = 0ull, a1 = 0ull, a2 = 0ull, a3 = 0ull;
        #pragma unroll
        for (int cc = 0; cc < 16; cc += 4) {
            ull x0, x1, x2, x3, x4, x5, x6, x7;
            asm volatile("ld.shared.v2.b64 {%0,%1},[%2];" : "=l"(x0), "=l"(x1) : "r"(sb + cc * 32));
            asm volatile("ld.shared.v2.b64 {%0,%1},[%2];" : "=l"(x2), "=l"(x3) : "r"(sb + cc * 32 + 32));
            asm volatile("ld.shared.v2.b64 {%0,%1},[%2];" : "=l"(x4), "=l"(x5) : "r"(sb + cc * 32 + 64));
            asm volatile("ld.shared.v2.b64 {%0,%1},[%2];" : "=l"(x6), "=l"(x7) : "r"(sb + cc * 32 + 96));
            a0 = ffma2(E2[2 * cc + 0], x0, a0);
            a1 = ffma2(E2[2 * cc + 1], x1, a1);
            a2 = ffma2(E2[2 * cc + 2], x2, a2);
            a3 = ffma2(E2[2 * cc + 3], x3, a3);
            a0 = ffma2(E2[2 * cc + 4], x4, a0);
            a1 = ffma2(E2[2 * cc + 5], x5, a1);
            a2 = ffma2(E2[2 * cc + 6], x6, a2);
            a3 = ffma2(E2[2 * cc + 7], x7, a3);
        }
        ull s = addf2(addf2(a0, a1), addf2(a2, a3));
        float lo, hi;
        unpackf2(s, lo, hi);
        float pdot = lo + hi;
        // combine the two k-halves (lane-adjacent pair)
        pdot += __shfl_xor_sync(0xffffffffu, pdot, 1);
        float dot = pdot * corr;

        // P_new = exp(emit - c) * dot ;  alpha = log P + M
        P = __expf(e0 - c) * dot;
        M += c + lcorr;
        corr = 1.0f; lcorr = 0.0f;
        e0 = e1; e1 = e2; e2 = e3; e3 = e4;

        if (t != len - 1) {
            // lazy renorm every 4 steps: publish warp maxes through this
            // step's barrier; applied to next step's dot.
            bool rn = ((t & 3) == 3);
            if (rn) {
                float mv = P;   // duplicated across pair — harmless for max
                #pragma unroll
                for (int o = 16; o > 0; o >>= 1)
                    mv = fmaxf(mv, __shfl_xor_sync(0xffffffffu, mv, o));
                if ((tid & 31) == 0) wmax[tid >> 5] = mv;
            }
            if (h == 0) buf[(t + 1) & 1][j] = P;
            __syncthreads();
            if (rn) {
                float mx = fmaxf(fmaxf(fmaxf(wmax[0], wmax[1]), fmaxf(wmax[2], wmax[3])),
                                 fmaxf(fmaxf(wmax[4], wmax[5]), fmaxf(wmax[6], wmax[7])));
                corr = __frcp_rn(mx);
                lcorr = __logf(mx);
            }
        }
    }

    // terminal: logsumexp_j( alpha[j] + trans[STOP, j] );  each j duplicated
    // across the pair — max is dup-safe, sum counts only h==0.
    float term = __logf(fmaxf(P, 1e-37f)) + M + trans[STOP_TAG * KK + j];
    float tm = block_max8(term, red);
    float contrib = (h == 0) ? __expf(term - tm) : 0.0f;
    float ssum = block_sum8(contrib, red);
    float fwd = tm + __logf(ssum);

    // gold score (each t exactly once across 256 threads)
    const int* trow = tags + b * TT;
    float g = 0.0f;
    for (int t = tid; t < TT; t += NTHR) {
        if (t < len) {
            int tag  = trow[t];
            int prev = (t == 0) ? START_TAG : trow[t - 1];
            g += trans[tag * KK + prev] + frow[t * KK + tag];
        }
    }
    if (tid == 0) g += trans[STOP_TAG * KK + trow[len - 1]];
    float gold = block_sum8(g, red);

    if (tid == 0) g_absdiff[b] = fabsf(fwd - gold);
}

// -------- deterministic final reduction --------
__global__ void reduce_kernel(float* __restrict__ out, int out_size) {
    __shared__ float s[BB];
    int t = threadIdx.x;
    s[t] = g_absdiff[t];
    __syncthreads();
    #pragma unroll
    for (int off = 256; off > 0; off >>= 1) {
        if (t < off) s[t] += s[t + off];
        __syncthreads();
    }
    float r = s[0] * (1.0f / (float)BB);
    for (int i = t; i < out_size; i += BB) out[i] = r;
}

extern "C" void kernel_launch(void* const* d_in, const int* in_sizes, int n_in,
                              void* d_out, int out_size) {
    const float* feats   = nullptr;
    const float* trans   = nullptr;
    const int*   tags    = nullptr;
    const int*   lengths = nullptr;
    for (int i = 0; i < n_in; i++) {
        switch (in_sizes[i]) {
            case BB * TT * KK: feats   = (const float*)d_in[i]; break;  // 33554432
            case KK * KK:      trans   = (const float*)d_in[i]; break;  // 16384
            case BB * TT:      tags    = (const int*)d_in[i];   break;  // 262144
            case BB:           lengths = (const int*)d_in[i];   break;  // 512
            default: break;
        }
    }

    // Launch order chosen so crf_kernel is launch #4 — the one ncu captures.
    order_kernel<<<1, BB>>>(lengths);
    shat_kernel<<<1, KK>>>(trans);
    zinit_kernel<<<1, BB>>>();
    crf_kernel<<<BB, NTHR>>>(feats, trans, tags, lengths);
    reduce_kernel<<<1, BB>>>((float*)d_out, out_size);
}